// round 5
// baseline (speedup 1.0000x reference)
#include <cuda_runtime.h>

// Fold: x (B=8, C=32, K1=8, K2=8, L=4096) -> out (B, C, H=260, W=260)
// kernel (8,8), stride (4,4), n = 64.
// Warp-aligned split: main region covers ow 0..255 (q = tid & 63 -> every
// warp holds 32 consecutive quads of ONE output row; all 16 warp-LDGs are
// single-line coalesced). Tail region covers the q=64 column (1/65 of work,
// reads are L2 hits on lines the main region fetches anyway).

namespace {
constexpr int B = 8;
constexpr int C = 32;
constexpr int K = 8;
constexpr int N = 64;               // patch grid
constexpr int L = N * N;            // 4096
constexpr int H = 260;
constexpr int W = 260;

constexpr int MAIN_Q = 64;                       // quads 0..63 per row
constexpr int MAIN_T = B * C * H * MAIN_Q;       // 4,259,840 = 16640*256
constexpr int MAIN_BLOCKS = MAIN_T / 256;        // 16640
constexpr int TAIL_T = B * C * H;                // 66,560 = 260*256
constexpr int TAIL_BLOCKS = TAIL_T / 256;        // 260
}

__device__ __forceinline__ float ldg_256(const float* p) {
    float v;
    asm volatile("ld.global.nc.L2::256B.f32 %0, [%1];" : "=f"(v) : "l"(p));
    return v;
}

__global__ __launch_bounds__(256) void fold_split_kernel(
    const float* __restrict__ x, float* __restrict__ out) {
    if (blockIdx.x < MAIN_BLOCKS) {
        // ---- main region: q = 0..63, vj0 always true ----
        int tid = blockIdx.x * 256 + threadIdx.x;
        int q   = tid & 63;
        int t   = tid >> 6;          // 0..66559
        int oh  = t % H;
        int bc  = t / H;

        const float* __restrict__ xb = x + (long long)bc * (K * K * L);

        int di0 = oh & 3;
        int di1 = di0 + 4;
        int i0  = oh >> 2;           // may be 64 (invalid) when oh >= 256
        int i1  = i0 - 1;            // may be -1 when oh < 4

        bool vi0 = i0 < N;
        bool vi1 = i1 >= 0;
        bool vj1 = q >= 1;

        int row0 = i0 * N;
        int row1 = i1 * N;

        bool v01 = vi0 && vj1;
        bool v11 = vi1 && vj1;

        float a[4], b[4], c[4], d[4];
#pragma unroll
        for (int r = 0; r < 4; r++) {
            a[r] = vi0 ? ldg_256(xb + (di0 * K + r) * L + row0 + q) : 0.f;
            b[r] = v01 ? ldg_256(xb + (di0 * K + r + 4) * L + row0 + q - 1) : 0.f;
            c[r] = vi1 ? ldg_256(xb + (di1 * K + r) * L + row1 + q) : 0.f;
            d[r] = v11 ? ldg_256(xb + (di1 * K + r + 4) * L + row1 + q - 1) : 0.f;
        }

        float4 o;
        o.x = (a[0] + b[0]) + (c[0] + d[0]);
        o.y = (a[1] + b[1]) + (c[1] + d[1]);
        o.z = (a[2] + b[2]) + (c[2] + d[2]);
        o.w = (a[3] + b[3]) + (c[3] + d[3]);

        float4* outv = (float4*)(out + (long long)bc * (H * W) + oh * W);
        outv[q] = o;
    } else {
        // ---- tail region: q = 64 (ow 256..259); only dj1 planes, col 63 ----
        int idx = (blockIdx.x - MAIN_BLOCKS) * 256 + threadIdx.x;  // 0..66559
        int oh  = idx % H;
        int bc  = idx / H;

        const float* __restrict__ xb = x + (long long)bc * (K * K * L);

        int di0 = oh & 3;
        int di1 = di0 + 4;
        int i0  = oh >> 2;
        int i1  = i0 - 1;

        bool vi0 = i0 < N;
        bool vi1 = i1 >= 0;

        int row0 = i0 * N;
        int row1 = i1 * N;

        float b[4], d[4];
#pragma unroll
        for (int r = 0; r < 4; r++) {
            b[r] = vi0 ? ldg_256(xb + (di0 * K + r + 4) * L + row0 + 63) : 0.f;
            d[r] = vi1 ? ldg_256(xb + (di1 * K + r + 4) * L + row1 + 63) : 0.f;
        }

        float4 o;
        o.x = b[0] + d[0];
        o.y = b[1] + d[1];
        o.z = b[2] + d[2];
        o.w = b[3] + d[3];

        float4* outv = (float4*)(out + (long long)bc * (H * W) + oh * W + 256);
        *outv = o;
    }
}

extern "C" void kernel_launch(void* const* d_in, const int* in_sizes, int n_in,
                              void* d_out, int out_size) {
    const float* x = (const float*)d_in[0];
    float* out = (float*)d_out;
    fold_split_kernel<<<MAIN_BLOCKS + TAIL_BLOCKS, 256>>>(x, out);  // 16900
}

// round 6
// speedup vs baseline: 1.1628x; 1.1628x over previous
#include <cuda_runtime.h>

// Fold: x (B=8, C=32, K1=8, K2=8, L=4096) -> out (B, C, H=260, W=260)
// kernel (8,8), stride (4,4), n = 64.
// R4 quad-gather (proven best: tid-contiguous load+store streams, minimal
// 322MB traffic) + streaming stores (st.global.cs): output is write-once-
// never-read, so evict-first keeps L2 for the read stream's q/q-1 dedup.

namespace {
constexpr int B = 8;
constexpr int C = 32;
constexpr int K = 8;
constexpr int N = 64;               // patch grid
constexpr int L = N * N;            // 4096
constexpr int H = 260;
constexpr int W = 260;
constexpr int QW = W / 4;           // 65 quads per row
constexpr int TOTAL_Q = B * C * H * QW;  // 4,326,400 = 16900 * 256 exactly
}

__device__ __forceinline__ float ldg_256(const float* p) {
    float v;
    asm volatile("ld.global.nc.L2::256B.f32 %0, [%1];" : "=f"(v) : "l"(p));
    return v;
}

__device__ __forceinline__ void stg_cs128(float4* p, float4 v) {
    asm volatile("st.global.cs.v4.f32 [%0], {%1, %2, %3, %4};"
                 :: "l"(p), "f"(v.x), "f"(v.y), "f"(v.z), "f"(v.w)
                 : "memory");
}

__global__ __launch_bounds__(256) void fold_quad_cs_kernel(
    const float* __restrict__ x, float* __restrict__ out) {
    int tid = blockIdx.x * blockDim.x + threadIdx.x;   // grid exact, no tail

    int q  = tid % QW;          // 0..64
    int t  = tid / QW;
    int oh = t % H;             // 0..259
    int bc = t / H;             // 0..255

    const float* __restrict__ xb = x + (long long)bc * (K * K * L);

    int di0 = oh & 3;
    int di1 = di0 + 4;
    int i0  = oh >> 2;          // row for di0 (may be 64 == invalid)
    int i1  = i0 - 1;           // row for di1 (may be -1)

    bool vi0 = i0 < N;
    bool vi1 = i1 >= 0;
    bool vj0 = q < N;           // q may be 64 on last quad
    bool vj1 = q >= 1;

    int row0 = i0 * N;
    int row1 = i1 * N;

    bool v00 = vi0 && vj0, v01 = vi0 && vj1;
    bool v10 = vi1 && vj0, v11 = vi1 && vj1;

    float a[4], b[4], c[4], d[4];
#pragma unroll
    for (int r = 0; r < 4; r++) {
        a[r] = v00 ? ldg_256(xb + (di0 * K + r) * L + row0 + q) : 0.f;
        b[r] = v01 ? ldg_256(xb + (di0 * K + r + 4) * L + row0 + q - 1) : 0.f;
        c[r] = v10 ? ldg_256(xb + (di1 * K + r) * L + row1 + q) : 0.f;
        d[r] = v11 ? ldg_256(xb + (di1 * K + r + 4) * L + row1 + q - 1) : 0.f;
    }

    float4 o;
    o.x = (a[0] + b[0]) + (c[0] + d[0]);
    o.y = (a[1] + b[1]) + (c[1] + d[1]);
    o.z = (a[2] + b[2]) + (c[2] + d[2]);
    o.w = (a[3] + b[3]) + (c[3] + d[3]);

    float4* outv = (float4*)(out + (long long)bc * (H * W) + oh * W) + q;
    stg_cs128(outv, o);
}

extern "C" void kernel_launch(void* const* d_in, const int* in_sizes, int n_in,
                              void* d_out, int out_size) {
    const float* x = (const float*)d_in[0];
    float* out = (float*)d_out;
    int threads = 256;
    int blocks = TOTAL_Q / threads;  // 16,900 exactly
    fold_quad_cs_kernel<<<blocks, threads>>>(x, out);
}